// round 1
// baseline (speedup 1.0000x reference)
#include <cuda_runtime.h>

#define NTOT 200      // histogram bins (STOP/DELTA)
#define TA   256      // A-rows per block (1 per thread)
#define BC   512      // B-points per block chunk (shared tile)
#define MAXPTS 16384

// Scratch: scaled positions with precomputed squared norm (x,y,z,|p|^2),
// and three raw integer histograms: [0]=00-triangle, [1]=01-cross, [2]=11-triangle.
__device__ float4 g_pts[MAXPTS];
__device__ int    g_hist[3 * NTOT];

__global__ __launch_bounds__(256) void prep_kernel(
    const float* __restrict__ pos0, int n0,
    const float* __restrict__ pos1, int n1,
    const float* __restrict__ rs)
{
    int idx = blockIdx.x * blockDim.x + threadIdx.x;
    float r0 = rs[0], r1 = rs[1], r2 = rs[2];
    if (idx < n0) {
        float x = pos0[idx * 3 + 0] * r0;
        float y = pos0[idx * 3 + 1] * r1;
        float z = pos0[idx * 3 + 2] * r2;
        float t = x * x; t = fmaf(y, y, t); t = fmaf(z, z, t);
        g_pts[idx] = make_float4(x, y, z, t);
    }
    if (idx < n1) {
        float x = pos1[idx * 3 + 0] * r0;
        float y = pos1[idx * 3 + 1] * r1;
        float z = pos1[idx * 3 + 2] * r2;
        float t = x * x; t = fmaf(y, y, t); t = fmaf(z, z, t);
        g_pts[n0 + idx] = make_float4(x, y, z, t);
    }
    if (idx < 3 * NTOT) g_hist[idx] = 0;
}

__device__ __forceinline__ float fsqrt_approx(float x) {
    float r;
    asm("sqrt.approx.f32 %0, %1;" : "=f"(r) : "f"(x));
    return r;
}

// One block = TA rows of A x BC columns of B. Shared histogram, then 200
// global atomics per block. SAME => only count j > i (triangle), doubled later.
template <bool SAME>
__global__ __launch_bounds__(256) void pair_kernel(
    int aOff, int nA, int bOff, int nB, int histIdx)
{
    __shared__ float4 sB[BC];
    __shared__ int    sh[NTOT];

    const int rowStart  = blockIdx.x * TA;
    const int chunkBase = blockIdx.y * BC;
    // Triangle cull: if max j in this chunk <= min i in this row block, nothing to do.
    if (SAME && (chunkBase + BC - 1) <= rowStart) return;

    const int tid = threadIdx.x;
    if (tid < NTOT) sh[tid] = 0;

    #pragma unroll
    for (int k = tid; k < BC; k += TA) {
        int j = chunkBase + k;
        sB[k] = (j < nB) ? g_pts[bOff + j] : make_float4(0.f, 0.f, 0.f, 1e30f);
    }
    __syncthreads();

    const int i = rowStart + tid;
    float4 a = (i < nA) ? g_pts[aOff + i] : make_float4(0.f, 0.f, 0.f, 1e30f);

    #pragma unroll 4
    for (int k = 0; k < BC; k++) {
        float4 b = sB[k];
        float t = a.x * b.x;
        t = fmaf(a.y, b.y, t);
        t = fmaf(a.z, b.z, t);
        // d2 = (a2 + b2) - 2*dot, single-rounded exactly like the reference's
        // s - 2t (the 2t product is exact).
        float d2 = fmaf(-2.0f, t, a.w + b.w);
        float fb = fsqrt_approx(fmaxf(d2, 0.0f)) * 20.0f;  // 1/DELTA = 20
        bool ok = (fb < (float)NTOT);
        if (SAME) ok = ok && ((chunkBase + k) > i);
        if (ok) atomicAdd(&sh[(int)fb], 1);
    }
    __syncthreads();

    if (tid < NTOT) {
        int v = sh[tid];
        if (v) atomicAdd(&g_hist[histIdx * NTOT + tid], v);
    }
}

__global__ void finalize_kernel(const float* __restrict__ count_in,
                                float* __restrict__ out,
                                const float* __restrict__ rs,
                                int n0, int n1)
{
    int idx = blockIdx.x * blockDim.x + threadIdx.x;
    if (idx >= 4 * NTOT) return;
    int k  = idx % NTOT;
    int ij = idx / NTOT;                       // i*2 + j
    int histIdx = (ij == 0) ? 0 : ((ij == 3) ? 2 : 1);
    float mult  = (ij == 0 || ij == 3) ? 2.0f : 1.0f;  // triangle -> full matrix
    float na = (float)((ij >> 1) ? n1 : n0);
    float nb = (float)((ij & 1) ? n1 : n0);
    float vol = rs[0] * rs[1] * rs[2];

    float counts = (float)g_hist[histIdx * NTOT + k] * mult;
    // SLICE_VOL[k] = (delta/2 + k*delta) * delta * 2*pi*3, computed in f64 then
    // cast to f32 (matches numpy).
    double r = 0.025 + (double)k * 0.05;
    float sv = (float)(r * 0.05 * 2.0 * 3.14159265358979323846 * 3.0);
    float density = nb / vol;
    float res = counts / density / sv / na;   // same division order as reference
    out[idx] = count_in[idx] + res;
}

extern "C" void kernel_launch(void* const* d_in, const int* in_sizes, int n_in,
                              void* d_out, int out_size)
{
    const float* pos0  = (const float*)d_in[0];
    const float* pos1  = (const float*)d_in[1];
    const float* count = (const float*)d_in[2];
    const float* rs    = (const float*)d_in[3];
    int n0 = in_sizes[0] / 3;
    int n1 = in_sizes[1] / 3;
    float* out = (float*)d_out;

    int nprep = n0 > n1 ? n0 : n1;
    if (nprep < 3 * NTOT) nprep = 3 * NTOT;
    prep_kernel<<<(nprep + 255) / 256, 256>>>(pos0, n0, pos1, n1, rs);

    // 0-0 triangle
    dim3 g00((n0 + TA - 1) / TA, (n0 + BC - 1) / BC);
    pair_kernel<true><<<g00, 256>>>(0, n0, 0, n0, 0);
    // 0-1 cross (serves both out[0][1] and out[1][0])
    dim3 g01((n0 + TA - 1) / TA, (n1 + BC - 1) / BC);
    pair_kernel<false><<<g01, 256>>>(0, n0, n0, n1, 1);
    // 1-1 triangle
    dim3 g11((n1 + TA - 1) / TA, (n1 + BC - 1) / BC);
    pair_kernel<true><<<g11, 256>>>(n0, n1, n0, n1, 2);

    finalize_kernel<<<(4 * NTOT + 255) / 256, 256>>>(count, out, rs, n0, n1);
}

// round 2
// speedup vs baseline: 2.6633x; 2.6633x over previous
#include <cuda_runtime.h>

#define NTOT 200      // histogram bins
#define TILE 256      // A-rows per block == B-cols per chunk == threads per block
#define NWARP 8
#define MAXPTS 16384

// Scaled positions (x,y,z prescaled by real_size*20, w = |p|^2) and 3 raw
// integer histograms: [0]=00-triangle, [1]=01-cross, [2]=11-triangle.
__device__ float4 g_pts[MAXPTS];
__device__ int    g_hist[3 * NTOT];

__global__ __launch_bounds__(256) void prep_kernel(
    const float* __restrict__ pos0, int n0,
    const float* __restrict__ pos1, int n1,
    const float* __restrict__ rs)
{
    int idx = blockIdx.x * blockDim.x + threadIdx.x;
    // prescale by INV_DELTA=20 so bin = floor(sqrt(d2)) directly
    float r0 = rs[0] * 20.0f, r1 = rs[1] * 20.0f, r2 = rs[2] * 20.0f;
    if (idx < n0) {
        float x = pos0[idx * 3 + 0] * r0;
        float y = pos0[idx * 3 + 1] * r1;
        float z = pos0[idx * 3 + 2] * r2;
        float t = x * x; t = fmaf(y, y, t); t = fmaf(z, z, t);
        g_pts[idx] = make_float4(x, y, z, t);
    }
    if (idx < n1) {
        float x = pos1[idx * 3 + 0] * r0;
        float y = pos1[idx * 3 + 1] * r1;
        float z = pos1[idx * 3 + 2] * r2;
        float t = x * x; t = fmaf(y, y, t); t = fmaf(z, z, t);
        g_pts[n0 + idx] = make_float4(x, y, z, t);
    }
    if (idx < 3 * NTOT) g_hist[idx] = 0;
}

__device__ __forceinline__ float fsqrt_approx(float x) {
    float r;
    asm("sqrt.approx.f32 %0, %1;" : "=f"(r) : "f"(x));
    return r;
}

// Invert upper-triangle linear index t -> (bi, bj), bj >= bi, n tiles per side.
// start(b) = b*(2n-b+1)/2.
__device__ __forceinline__ void tri_decode(int t, int n, int& bi, int& bj) {
    float fn = (float)(2 * n + 1);
    int b = (int)((fn - sqrtf(fmaxf(fn * fn - 8.0f * (float)t, 0.0f))) * 0.5f);
    if (b < 0) b = 0;
    if (b > n - 1) b = n - 1;
    while (b > 0 && t < b * (2 * n - b + 1) / 2) b--;
    while (b < n - 1 && t >= (b + 1) * (2 * n - b) / 2) b++;
    bi = b;
    bj = b + (t - b * (2 * n - b + 1) / 2);
}

// One fused kernel covering all three pair regions, one full wave of blocks.
__global__ __launch_bounds__(256) void pair_fused_kernel(
    int n0, int n1, int nb0, int nb1, int T0, int C)
{
    __shared__ float4 sB[TILE];
    __shared__ int    sh[NWARP * NTOT];

    // ---- decode block -> work unit ----
    int w = blockIdx.x;
    int bi, bj, aOff, bOff, nA, nB, histIdx;
    bool diag;
    if (w < T0) {                     // 0-0 triangle
        tri_decode(w, nb0, bi, bj);
        aOff = 0; bOff = 0; nA = n0; nB = n0; histIdx = 0;
        diag = (bi == bj);
    } else if (w < T0 + C) {          // 0-1 cross
        int u = w - T0;
        bi = u / nb1; bj = u % nb1;
        aOff = 0; nA = n0; bOff = n0; nB = n1; histIdx = 1;
        diag = false;
    } else {                          // 1-1 triangle
        int u = w - T0 - C;
        tri_decode(u, nb1, bi, bj);
        aOff = n0; bOff = n0; nA = n1; nB = n1; histIdx = 2;
        diag = (bi == bj);
    }
    const int rowStart  = bi * TILE;
    const int chunkBase = bj * TILE;
    const int tid = threadIdx.x;
    const int wid = tid >> 5;
    int* myh = &sh[wid * NTOT];

    #pragma unroll
    for (int idx = tid; idx < NWARP * NTOT; idx += 256) sh[idx] = 0;

    {
        int j = chunkBase + tid;
        sB[tid] = (j < nB) ? g_pts[bOff + j]
                           : make_float4(0.f, 0.f, 0.f, 1e30f);
    }
    __syncthreads();

    const int i = rowStart + tid;
    float4 a = (i < nA) ? g_pts[aOff + i] : make_float4(0.f, 0.f, 0.f, 1e30f);
    // fold -2 into a copy: d2 = (a.w + b.w) + (-2ax)bx + (-2ay)by + (-2az)bz
    float ax2 = -2.0f * a.x, ay2 = -2.0f * a.y, az2 = -2.0f * a.z, aw = a.w;

    if (diag) {
        #pragma unroll 8
        for (int k = 0; k < TILE; k++) {
            float4 b = sB[k];
            float t = aw + b.w;
            t = fmaf(ax2, b.x, t);
            t = fmaf(ay2, b.y, t);
            t = fmaf(az2, b.z, t);
            float d = fsqrt_approx(fmaxf(t, 0.0f));
            if (d < (float)NTOT && (chunkBase + k) > i)
                atomicAdd(&myh[(int)d], 1);
        }
    } else {
        #pragma unroll 8
        for (int k = 0; k < TILE; k++) {
            float4 b = sB[k];
            float t = aw + b.w;
            t = fmaf(ax2, b.x, t);
            t = fmaf(ay2, b.y, t);
            t = fmaf(az2, b.z, t);
            float d = fsqrt_approx(fmaxf(t, 0.0f));
            if (d < (float)NTOT)
                atomicAdd(&myh[(int)d], 1);
        }
    }
    __syncthreads();

    if (tid < NTOT) {
        int v = 0;
        #pragma unroll
        for (int ww = 0; ww < NWARP; ww++) v += sh[ww * NTOT + tid];
        if (v) atomicAdd(&g_hist[histIdx * NTOT + tid], v);
    }
}

__global__ void finalize_kernel(const float* __restrict__ count_in,
                                float* __restrict__ out,
                                const float* __restrict__ rs,
                                int n0, int n1)
{
    int idx = blockIdx.x * blockDim.x + threadIdx.x;
    if (idx >= 4 * NTOT) return;
    int k  = idx % NTOT;
    int ij = idx / NTOT;                       // i*2 + j
    int histIdx = (ij == 0) ? 0 : ((ij == 3) ? 2 : 1);
    float mult  = (ij == 0 || ij == 3) ? 2.0f : 1.0f;  // triangle -> full
    float na = (float)((ij >> 1) ? n1 : n0);
    float nb = (float)((ij & 1) ? n1 : n0);
    float vol = rs[0] * rs[1] * rs[2];

    float counts = (float)g_hist[histIdx * NTOT + k] * mult;
    double r = 0.025 + (double)k * 0.05;
    float sv = (float)(r * 0.05 * 2.0 * 3.14159265358979323846 * 3.0);
    float density = nb / vol;
    float res = counts / density / sv / na;   // same division order as ref
    out[idx] = count_in[idx] + res;
}

extern "C" void kernel_launch(void* const* d_in, const int* in_sizes, int n_in,
                              void* d_out, int out_size)
{
    const float* pos0  = (const float*)d_in[0];
    const float* pos1  = (const float*)d_in[1];
    const float* count = (const float*)d_in[2];
    const float* rs    = (const float*)d_in[3];
    int n0 = in_sizes[0] / 3;
    int n1 = in_sizes[1] / 3;
    float* out = (float*)d_out;

    int nprep = n0 > n1 ? n0 : n1;
    if (nprep < 3 * NTOT) nprep = 3 * NTOT;
    prep_kernel<<<(nprep + 255) / 256, 256>>>(pos0, n0, pos1, n1, rs);

    int nb0 = (n0 + TILE - 1) / TILE;
    int nb1 = (n1 + TILE - 1) / TILE;
    int T0 = nb0 * (nb0 + 1) / 2;
    int C  = nb0 * nb1;
    int T1 = nb1 * (nb1 + 1) / 2;
    pair_fused_kernel<<<T0 + C + T1, 256>>>(n0, n1, nb0, nb1, T0, C);

    finalize_kernel<<<(4 * NTOT + 255) / 256, 256>>>(count, out, rs, n0, n1);
}